// round 15
// baseline (speedup 1.0000x reference)
#include <cuda_runtime.h>

#define GS 32
#define G3 (GS * GS * GS)
#define NPTS 4096
#define NBATCH 256
#define WORDS_PER_BATCH (G3 / 32)          // 1024 words = 4KB per batch

// Device scratch (static globals — no allocation). g_acc is zero-initialized
// at module load; final_kernel resets it after reading, so every invocation
// (correctness call and each graph replay) starts from zero.
__device__ unsigned g_vox[NBATCH * WORDS_PER_BATCH];   // 1 MB bitmask
__device__ double   g_acc[2];

// ---------------------------------------------------------------------------
// Pack voxel (float 0.0/1.0) into a bitmask: 32 MB stream read -> 1 MB write.
// ---------------------------------------------------------------------------
__global__ void __launch_bounds__(256)
pack_kernel(const float* __restrict__ voxel) {
    unsigned i = blockIdx.x * 256u + threadIdx.x;
    float v = voxel[i];
    unsigned bits = __ballot_sync(0xffffffffu, v != 0.f);
    if ((threadIdx.x & 31) == 0) g_vox[i >> 5] = bits;
}

// ---------------------------------------------------------------------------
// Main loss kernel. Grid = (8, NBATCH), batch-major: the 8 CTAs of a batch
// co-run so its 384KB cp slice stays L2-resident. The batch's 4KB voxel
// bitmask is staged into SHARED memory (immune to L1 thrash from the cp
// gather stream; probes are 29-cyc LDS on a separate port).
// Each thread owns exactly 2 points, pushed through wide phases:
//   phase 1: 12 affine transforms + flattened indices (pure FMA)
//   phase 2: 12 smem bitmask probes
//   phase 3: conditional cp gathers + distance accumulate
// Transforms built per-block by threads 0..5 — no setup kernel.
// ---------------------------------------------------------------------------
__global__ void __launch_bounds__(256)
loss_kernel(const float* __restrict__ points,
            const float* __restrict__ cp,
            const float* __restrict__ plane,
            const float* __restrict__ quat) {
    __shared__ float    xf[72];
    __shared__ unsigned smask[WORDS_PER_BATCH];   // 4KB per-batch bitmask
    __shared__ float    red[2][8];

    int tid = threadIdx.x;
    int b   = blockIdx.y;

    if (tid < 3) {
        // Plane reflection: A = I - (2/s) n n^T, b = -(2d/s) n
        float nx = plane[tid * 4 + 0], ny = plane[tid * 4 + 1];
        float nz = plane[tid * 4 + 2], d  = plane[tid * 4 + 3];
        float inv = 2.0f / (nx * nx + ny * ny + nz * nz);
        float* A = &xf[tid * 12];
        A[0] = 1.f - inv * nx * nx; A[1] =      -inv * nx * ny; A[2] =      -inv * nx * nz;
        A[3] =      -inv * ny * nx; A[4] = 1.f - inv * ny * ny; A[5] =      -inv * ny * nz;
        A[6] =      -inv * nz * nx; A[7] =      -inv * nz * ny; A[8] = 1.f - inv * nz * nz;
        A[9]  = -inv * d * nx;
        A[10] = -inv * d * ny;
        A[11] = -inv * d * nz;
    } else if (tid < 6) {
        // Quaternion rotation matrix (unit quaternion).
        int i = tid - 3;
        float q0 = quat[i * 4 + 0], q1 = quat[i * 4 + 1];
        float q2 = quat[i * 4 + 2], q3 = quat[i * 4 + 3];
        float nrm = sqrtf(q0 * q0 + q1 * q1 + q2 * q2 + q3 * q3);
        float w = q0 / nrm, x = q1 / nrm, y = q2 / nrm, z = q3 / nrm;
        float* A = &xf[tid * 12];
        A[0] = 1.f - 2.f * (y * y + z * z);
        A[1] = 2.f * (x * y - w * z);
        A[2] = 2.f * (x * z + w * y);
        A[3] = 2.f * (x * y + w * z);
        A[4] = 1.f - 2.f * (x * x + z * z);
        A[5] = 2.f * (y * z - w * x);
        A[6] = 2.f * (x * z - w * y);
        A[7] = 2.f * (y * z + w * x);
        A[8] = 1.f - 2.f * (x * x + y * y);
        A[9] = A[10] = A[11] = 0.f;
    }

    // Stage this batch's bitmask into shared (coalesced, 4 words/thread).
    {
        const unsigned* vb = g_vox + (size_t)b * WORDS_PER_BATCH;
#pragma unroll
        for (int i = tid; i < WORDS_PER_BATCH; i += 256) smask[i] = vb[i];
    }
    __syncthreads();

    const float* pb  = points + (size_t)b * NPTS * 3;
    const float* cpb = cp     + (size_t)b * G3 * 3;

    const float gm = -0.484375f;  // grid_min = -0.5 + 0.5/32 (exact in fp32)

    // Exactly 2 points per thread: n0 and n0 + 2048.
    int n0 = blockIdx.x * 256 + tid;

    float p[2][3];
#pragma unroll
    for (int h = 0; h < 2; h++) {
        int n = n0 + h * 2048;
        p[h][0] = pb[n * 3 + 0];
        p[h][1] = pb[n * 3 + 1];
        p[h][2] = pb[n * 3 + 2];
    }

    float txA[12], tyA[12], tzA[12];
    int   idxA[12];

    // ---- phase 1: 12 transforms + flattened cell indices ----
#pragma unroll
    for (int h = 0; h < 2; h++) {
#pragma unroll
        for (int t = 0; t < 6; t++) {
            const float* A = &xf[t * 12];
            int k = h * 6 + t;
            float tx = fmaf(A[0], p[h][0], fmaf(A[1], p[h][1], fmaf(A[2], p[h][2], A[9])));
            float ty = fmaf(A[3], p[h][0], fmaf(A[4], p[h][1], fmaf(A[5], p[h][2], A[10])));
            float tz = fmaf(A[6], p[h][0], fmaf(A[7], p[h][1], fmaf(A[8], p[h][2], A[11])));
            txA[k] = tx; tyA[k] = ty; tzA[k] = tz;

            float fx = rintf(fminf(fmaxf((tx - gm) * 32.f, 0.f), 31.f));
            float fy = rintf(fminf(fmaxf((ty - gm) * 32.f, 0.f), 31.f));
            float fz = rintf(fminf(fmaxf((tz - gm) * 32.f, 0.f), 31.f));
            // fx*1024+fy*32+fz <= 32767: exact in fp32 -> single F2I
            idxA[k] = (int)fmaf(fx, 1024.f, fmaf(fy, 32.f, fz));
        }
    }

    // ---- phase 2: 12 bitmask probes from shared memory ----
    unsigned wA[12];
#pragma unroll
    for (int k = 0; k < 12; k++) wA[k] = smask[idxA[k] >> 5];

    // ---- phase 3: conditional cp gathers + accumulate ----
    // bit set => voxel==1 => mask 0 => skip the 12B gather (~20% of evals).
    // Split accumulators halve the serial FADD dependency depth.
    float aR0 = 0.f, aQ0 = 0.f, aR1 = 0.f, aQ1 = 0.f;
#pragma unroll
    for (int k = 0; k < 12; k++) {
        if (!((wA[k] >> (idxA[k] & 31)) & 1u)) {
            const float* c = cpb + (size_t)idxA[k] * 3;
            float dx = txA[k] - __ldg(c + 0);
            float dy = tyA[k] - __ldg(c + 1);
            float dz = tzA[k] - __ldg(c + 2);
            float sq = fmaf(dx, dx, fmaf(dy, dy, dz * dz));
            bool refl = (k % 6) < 3;
            if (k < 6) { if (refl) aR0 += sq; else aQ0 += sq; }
            else       { if (refl) aR1 += sq; else aQ1 += sq; }
        }
    }
    float aR = aR0 + aR1;
    float aQ = aQ0 + aQ1;

    // Warp reduce, block reduce, one double atomic per block per loss.
#pragma unroll
    for (int o = 16; o > 0; o >>= 1) {
        aR += __shfl_down_sync(0xffffffffu, aR, o);
        aQ += __shfl_down_sync(0xffffffffu, aQ, o);
    }
    int lane = tid & 31, w = tid >> 5;
    if (lane == 0) { red[0][w] = aR; red[1][w] = aQ; }
    __syncthreads();
    if (tid == 0) {
        float sR = 0.f, sQ = 0.f;
#pragma unroll
        for (int i = 0; i < 8; i++) { sR += red[0][i]; sQ += red[1][i]; }
        atomicAdd(&g_acc[0], (double)sR);
        atomicAdd(&g_acc[1], (double)sQ);
    }
}

// ---------------------------------------------------------------------------
// Finalize: write means, then reset accumulators for the next invocation.
// ---------------------------------------------------------------------------
__global__ void final_kernel(float* __restrict__ out) {
    if (threadIdx.x == 0) {
        out[0] = (float)(g_acc[0] / (double)NBATCH);
        out[1] = (float)(g_acc[1] / (double)NBATCH);
        g_acc[0] = 0.0;
        g_acc[1] = 0.0;
    }
}

extern "C" void kernel_launch(void* const* d_in, const int* in_sizes, int n_in,
                              void* d_out, int out_size) {
    const float* points = (const float*)d_in[0];
    const float* cp     = (const float*)d_in[1];
    const float* voxel  = (const float*)d_in[2];
    const float* plane  = (const float*)d_in[3];
    const float* quat   = (const float*)d_in[4];

    pack_kernel<<<(NBATCH * G3) / 256, 256>>>(voxel);

    dim3 grid(8, NBATCH);          // batch-major: 8 CTAs x 256 thr per batch
    loss_kernel<<<grid, 256>>>(points, cp, plane, quat);

    final_kernel<<<1, 32>>>((float*)d_out);
}